// round 9
// baseline (speedup 1.0000x reference)
#include <cuda_runtime.h>
#include <cuda_fp16.h>
#include <cstdint>

#define BB   4
#define TT   2048
#define DIN  768
#define DOUT 768
#define NH   12
#define HD   64
#define MROWS (BB*TT)   // 8192
#define QKVSZ (BB*NH*TT*HD)

// ---------------------------------------------------------------------------
// Scratch (static device memory -- no allocations allowed)
// ---------------------------------------------------------------------------
__device__ __half g_xh  [MROWS*DIN];       // x -> fp16
__device__ __half g_QKV [3*QKVSZ];         // Q|K|V, [b,h,t,hd]; Q scaled by 0.125*log2e
__device__ __half g_ctx [MROWS*DOUT];      // [b,t,d]
__device__ __half g_Wh  [DIN*3*DOUT];      // [k][ Wq | Wk | Wv ] row-major fp16
__device__ __half g_WoH [DOUT*DOUT];       // Wo row-major fp16

// ---------------------------------------------------------------------------
// PTX helpers (baseline sm_75/80-class; harness targets compute_103, no 'a')
// ---------------------------------------------------------------------------
__device__ __forceinline__ uint32_t smem_u32(const void* p) {
    uint32_t a;
    asm("{ .reg .u64 t; cvta.to.shared.u64 t, %1; cvt.u32.u64 %0, t; }"
        : "=r"(a) : "l"(p));
    return a;
}

#define CP_ASYNC16(dst, src) \
    asm volatile("cp.async.cg.shared.global [%0], [%1], 16;" \
                 :: "r"(dst), "l"(src) : "memory")
#define CP_COMMIT() asm volatile("cp.async.commit_group;" ::: "memory")
#define CP_WAIT1()  asm volatile("cp.async.wait_group 1;" ::: "memory")
#define CP_WAIT0()  asm volatile("cp.async.wait_group 0;" ::: "memory")

__device__ __forceinline__ void ldsm4(uint32_t r[4], uint32_t addr) {
    asm volatile("ldmatrix.sync.aligned.m8n8.x4.shared.b16 {%0,%1,%2,%3}, [%4];"
        : "=r"(r[0]), "=r"(r[1]), "=r"(r[2]), "=r"(r[3]) : "r"(addr));
}
__device__ __forceinline__ void ldsm4t(uint32_t r[4], uint32_t addr) {
    asm volatile("ldmatrix.sync.aligned.m8n8.x4.trans.shared.b16 {%0,%1,%2,%3}, [%4];"
        : "=r"(r[0]), "=r"(r[1]), "=r"(r[2]), "=r"(r[3]) : "r"(addr));
}

__device__ __forceinline__ void mma_f16(float c[4], const uint32_t a[4],
                                        uint32_t b0, uint32_t b1) {
    asm volatile(
        "mma.sync.aligned.m16n8k16.row.col.f32.f16.f16.f32 "
        "{%0,%1,%2,%3}, {%4,%5,%6,%7}, {%8,%9}, {%0,%1,%2,%3};"
        : "+f"(c[0]), "+f"(c[1]), "+f"(c[2]), "+f"(c[3])
        : "r"(a[0]), "r"(a[1]), "r"(a[2]), "r"(a[3]), "r"(b0), "r"(b1));
}

__device__ __forceinline__ uint32_t packh2(float x, float y) {
    __half2 h = __floats2half2_rn(x, y);
    return *reinterpret_cast<uint32_t*>(&h);
}
__device__ __forceinline__ uint32_t h2ex2(uint32_t x) {
    uint32_t r;
    asm("ex2.approx.f16x2 %0, %1;" : "=r"(r) : "r"(x));
    return r;
}
__device__ __forceinline__ uint32_t hadd2u(uint32_t a, uint32_t b) {
    __half2 r = __hadd2(*reinterpret_cast<__half2*>(&a),
                        *reinterpret_cast<__half2*>(&b));
    return *reinterpret_cast<uint32_t*>(&r);
}

// ---------------------------------------------------------------------------
// fp32 -> fp16 (x)
// ---------------------------------------------------------------------------
__global__ __launch_bounds__(256)
void to_half(const float* __restrict__ in, __half* __restrict__ out)
{
    const size_t i = ((size_t)blockIdx.x * 256 + threadIdx.x) * 4;
    float4 v = *(const float4*)(in + i);
    uint2 u;
    u.x = packh2(v.x, v.y);
    u.y = packh2(v.z, v.w);
    *(uint2*)(out + i) = u;
}

// ---------------------------------------------------------------------------
// Merged weight conversion (row-major; GEMM consumes via ldmatrix.trans)
// ---------------------------------------------------------------------------
__global__ __launch_bounds__(256)
void conv_w(const float* __restrict__ Wq, const float* __restrict__ Wk,
            const float* __restrict__ Wv, const float* __restrict__ Wo,
            __half* __restrict__ Wh, __half* __restrict__ WoH)
{
    const int z = blockIdx.z;
    const float* src = (z == 0) ? Wq : (z == 1) ? Wk : (z == 2) ? Wv : Wo;
    const size_t i = ((size_t)blockIdx.x * 256 + threadIdx.x) * 4;
    float4 v = *(const float4*)(src + i);
    uint2 u;
    u.x = packh2(v.x, v.y);
    u.y = packh2(v.z, v.w);
    if (z < 3) {
        const int k = (int)(i / DOUT), n = (int)(i % DOUT);
        *(uint2*)(Wh + (size_t)k * (3 * DOUT) + z * DOUT + n) = u;
    } else {
        *(uint2*)(WoH + i) = u;
    }
}

// ---------------------------------------------------------------------------
// Pipelined fp16 mma.sync GEMM: C[128x128] = A @ W (W row-major via ldsm.trans)
// 3-stage cp.async pipeline, ONE __syncthreads per K-iter.
// EPI 0: fp32 + bias (final). EPI 1: fp16 head-split QKV (Q scaled).
// ---------------------------------------------------------------------------
template<int EPI>
__global__ __launch_bounds__(256)
void gemm_h(const __half* __restrict__ A, const __half* __restrict__ W,
            const float* __restrict__ bias, void* __restrict__ Cv,
            int Kd, int lda, int ldb, int ldc)
{
    constexpr int LDA_ = 72;
    constexpr int LDB_ = 136;
    constexpr int ASZ  = 128 * LDA_;        // halfs per A stage
    constexpr int BSZ  = 64 * LDB_;         // halfs per B stage

    extern __shared__ __half smh[];
    __half* As = smh;                        // [3][128][72]
    __half* Bs = smh + 3 * ASZ;              // [3][64][136]
    const uint32_t sbA = smem_u32(As);
    const uint32_t sbB = smem_u32(Bs);

    const int tid  = threadIdx.x;
    const int wid  = tid >> 5;
    const int lane = tid & 31;
    const int gidx = lane >> 2;
    const int ctig = lane & 3;
    const int bn = blockIdx.x * 128;
    const int bm = blockIdx.y * 128;

    const int warp_n = (wid & 3) * 32;
    const int warp_m = (wid >> 2) * 64;

    float acc[4][4][4];
#pragma unroll
    for (int mf = 0; mf < 4; mf++)
#pragma unroll
        for (int nf = 0; nf < 4; nf++)
#pragma unroll
            for (int q = 0; q < 4; q++) acc[mf][nf][q] = 0.f;

    const int nk = Kd >> 6;

    auto issue = [&](int it, int buf) {
        const int kt = it << 6;
#pragma unroll
        for (int j = 0; j < 4; j++) {
            const int seg = j * 256 + tid;
            const int r = seg >> 3, c = seg & 7;
            CP_ASYNC16(sbA + (uint32_t)(buf * ASZ + r * LDA_ + c * 8) * 2,
                       A + (size_t)(bm + r) * lda + kt + c * 8);
        }
#pragma unroll
        for (int j = 0; j < 4; j++) {
            const int seg = j * 256 + tid;
            const int r = seg >> 4, c = seg & 15;
            CP_ASYNC16(sbB + (uint32_t)(buf * BSZ + r * LDB_ + c * 8) * 2,
                       W + (size_t)(kt + r) * ldb + bn + c * 8);
        }
        CP_COMMIT();
    };

    issue(0, 0);
    issue(1, 1);

    const int arow = lane & 15;
    const int acol = (lane >> 4) << 3;
    const int vrow = ((lane >> 3) & 1) * 8 + (lane & 7);
    const int vcol = (lane >> 4) << 3;

    for (int i = 0; i < nk; i++) {
        const int buf = i % 3;
        if (i + 1 < nk) CP_WAIT1();
        else            CP_WAIT0();
        __syncthreads();                     // stage i published; compute(i-1) done

        if (i + 2 < nk) issue(i + 2, (i + 2) % 3);

        const uint32_t Ab = sbA + (uint32_t)(buf * ASZ) * 2;
        const uint32_t Bb = sbB + (uint32_t)(buf * BSZ) * 2;

#pragma unroll
        for (int ks = 0; ks < 4; ks++) {
            uint32_t afr[4][4];
#pragma unroll
            for (int mf = 0; mf < 4; mf++)
                ldsm4(afr[mf], Ab + (uint32_t)((warp_m + mf * 16 + arow) * LDA_
                                               + ks * 16 + acol) * 2);
            uint32_t bfr[2][4];
#pragma unroll
            for (int np = 0; np < 2; np++)
                ldsm4t(bfr[np], Bb + (uint32_t)((ks * 16 + vrow) * LDB_
                                                + warp_n + np * 16 + vcol) * 2);
#pragma unroll
            for (int mf = 0; mf < 4; mf++)
#pragma unroll
                for (int np = 0; np < 2; np++) {
                    mma_f16(acc[mf][2 * np],     afr[mf], bfr[np][0], bfr[np][1]);
                    mma_f16(acc[mf][2 * np + 1], afr[mf], bfr[np][2], bfr[np][3]);
                }
        }
    }

#pragma unroll
    for (int mf = 0; mf < 4; mf++) {
#pragma unroll
        for (int nf = 0; nf < 4; nf++) {
            const int row0 = bm + warp_m + mf * 16 + gidx;
            const int cl   = warp_n + nf * 8 + ctig * 2;
            if (EPI == 1) {
                __half* C = (__half*)Cv;
                const int mat = bn / DOUT;
                const float sc = (mat == 0) ? 0.125f * 1.44269504f : 1.f;
                const int cg  = bn + cl - mat * DOUT;
                const int h_  = cg >> 6, hd_ = cg & 63;
                const int b_  = row0 >> 11, t_ = row0 & (TT - 1);
                __half* d0 = C + (size_t)mat * QKVSZ
                           + (((size_t)(b_ * NH + h_) << 11) + t_) * HD + hd_;
                __half* d1 = d0 + 8 * HD;
                *(uint32_t*)d0 = packh2(acc[mf][nf][0] * sc, acc[mf][nf][1] * sc);
                *(uint32_t*)d1 = packh2(acc[mf][nf][2] * sc, acc[mf][nf][3] * sc);
            } else {
                float* C = (float*)Cv;
                float* d0 = C + (size_t)row0 * ldc + bn + cl;
                float* d1 = d0 + (size_t)8 * ldc;
                float b0 = 0.f, b1 = 0.f;
                if (bias) { b0 = bias[bn + cl]; b1 = bias[bn + cl + 1]; }
                *(float2*)d0 = make_float2(acc[mf][nf][0] + b0, acc[mf][nf][1] + b1);
                *(float2*)d1 = make_float2(acc[mf][nf][2] + b0, acc[mf][nf][3] + b1);
            }
        }
    }
}

// ---------------------------------------------------------------------------
// Fused flash attention v4: fp16 mma.sync + ldmatrix, no-max softmax,
// exp via ex2.approx.f16x2, l via HADD2 tree on the idle fma pipe
// (tensor pipe reserved for S and PV MMAs), 3-stage cp.async, 1 barrier/iter.
// ---------------------------------------------------------------------------
__global__ __launch_bounds__(256, 2)
void flash_attn(const __half* __restrict__ Q, const __half* __restrict__ K,
                const __half* __restrict__ V, __half* __restrict__ ctx)
{
    constexpr int LDH = 72;
    constexpr int QSZ = 128 * LDH;
    constexpr int KSZ = 64 * LDH;

    extern __shared__ __half smh[];
    __half* Qs = smh;                        // 128 x 72
    __half* Ks = smh + QSZ;                  // [3][64][72]
    __half* Vs = Ks + 3 * KSZ;               // [3][64][72]
    const uint32_t sbQ = smem_u32(Qs);
    const uint32_t sbK = smem_u32(Ks);
    const uint32_t sbV = smem_u32(Vs);

    const int tid  = threadIdx.x;
    const int wid  = tid >> 5;
    const int lane = tid & 31;
    const int gidx = lane >> 2;
    const int ctig = lane & 3;
    const int q0 = blockIdx.x * 128;
    const int bh = blockIdx.y;
    const int warp_m = wid * 16;

    const __half* Qb = Q + ((size_t)bh * TT + q0) * HD;
    const __half* Kb = K + (size_t)bh * TT * HD;
    const __half* Vb = V + (size_t)bh * TT * HD;

    // stage Q
#pragma unroll
    for (int j = 0; j < 4; j++) {
        const int seg = j * 256 + tid;
        const int r = seg >> 3, c = seg & 7;
        *(uint4*)(Qs + r * LDH + c * 8) = *(const uint4*)(Qb + r * HD + c * 8);
    }

    const int arow = lane & 15;
    const int acol = (lane >> 4) << 3;
    const int brow = ((lane >> 4) << 3) + (lane & 7);
    const int bcol = ((lane >> 3) & 1) * 8;
    const int vrow = ((lane >> 3) & 1) * 8 + (lane & 7);
    const int vcol = (lane >> 4) << 3;

    auto issueKV = [&](int blk, int buf) {
        const __half* kp = Kb + (size_t)blk * 64 * HD;
        const __half* vp = Vb + (size_t)blk * 64 * HD;
#pragma unroll
        for (int j = 0; j < 2; j++) {
            const int seg = j * 256 + tid;
            const int r = seg >> 3, c = seg & 7;
            CP_ASYNC16(sbK + (uint32_t)(buf * KSZ + r * LDH + c * 8) * 2,
                       kp + r * HD + c * 8);
        }
#pragma unroll
        for (int j = 0; j < 2; j++) {
            const int seg = j * 256 + tid;
            const int r = seg >> 3, c = seg & 7;
            CP_ASYNC16(sbV + (uint32_t)(buf * KSZ + r * LDH + c * 8) * 2,
                       vp + r * HD + c * 8);
        }
        CP_COMMIT();
    };

    issueKV(0, 0);
    issueKV(1, 1);
    __syncthreads();                         // Q staged (overlaps KV issue)

    uint32_t qf[4][4];
#pragma unroll
    for (int ks = 0; ks < 4; ks++)
        ldsm4(qf[ks], sbQ + (uint32_t)((warp_m + arow) * LDH + ks * 16 + acol) * 2);

    float O[8][4];
#pragma unroll
    for (int nf = 0; nf < 8; nf++)
#pragma unroll
        for (int q = 0; q < 4; q++) O[nf][q] = 0.f;
    float l0 = 0.f, l1 = 0.f;

    constexpr int NB = TT / 64;              // 32
    int buf = 0;

    for (int i = 0; i < NB; i++) {
        if (i + 1 < NB) CP_WAIT1();
        else            CP_WAIT0();
        __syncthreads();                     // publish stage i; prev compute done

        const uint32_t Kt = sbK + (uint32_t)(buf * KSZ) * 2;
        const uint32_t Vt = sbV + (uint32_t)(buf * KSZ) * 2;

        // ---- S' = (Q * 0.125*log2e) @ K^T ----
        float s[8][4];
#pragma unroll
        for (int nf = 0; nf < 8; nf++)
#pragma unroll
            for (int q = 0; q < 4; q++) s[nf][q] = 0.f;

#pragma unroll
        for (int ks = 0; ks < 4; ks++) {
#pragma unroll
            for (int np = 0; np < 4; np++) {
                uint32_t kf[4];
                ldsm4(kf, Kt + (uint32_t)((np * 16 + brow) * LDH + ks * 16 + bcol) * 2);
                mma_f16(s[2 * np],     qf[ks], kf[0], kf[1]);
                mma_f16(s[2 * np + 1], qf[ks], kf[2], kf[3]);
            }
        }

        // ---- P = exp2(S') in fp16x2 ----
        uint32_t ph[8][2];
#pragma unroll
        for (int nf = 0; nf < 8; nf++) {
            ph[nf][0] = h2ex2(packh2(s[nf][0], s[nf][1]));
            ph[nf][1] = h2ex2(packh2(s[nf][2], s[nf][3]));
        }

        // ---- l += row-sum(P) via HADD2 tree (fma pipe, not tensor) ----
        {
            uint32_t r0 = hadd2u(hadd2u(hadd2u(ph[0][0], ph[1][0]),
                                        hadd2u(ph[2][0], ph[3][0])),
                                 hadd2u(hadd2u(ph[4][0], ph[5][0]),
                                        hadd2u(ph[6][0], ph[7][0])));
            uint32_t r1 = hadd2u(hadd2u(hadd2u(ph[0][1], ph[1][1]),
                                        hadd2u(ph[2][1], ph[3][1])),
                                 hadd2u(hadd2u(ph[4][1], ph[5][1]),
                                        hadd2u(ph[6][1], ph[7][1])));
            float2 f0 = __half22float2(*reinterpret_cast<__half2*>(&r0));
            float2 f1 = __half22float2(*reinterpret_cast<__half2*>(&r1));
            l0 += f0.x + f0.y;
            l1 += f1.x + f1.y;
        }

        // ---- O += P @ V ----
#pragma unroll
        for (int j = 0; j < 4; j++) {
            uint32_t af[4];
            af[0] = ph[2 * j][0];
            af[1] = ph[2 * j][1];
            af[2] = ph[2 * j + 1][0];
            af[3] = ph[2 * j + 1][1];
#pragma unroll
            for (int np = 0; np < 4; np++) {
                uint32_t vf[4];
                ldsm4t(vf, Vt + (uint32_t)((j * 16 + vrow) * LDH + np * 16 + vcol) * 2);
                mma_f16(O[2 * np],     af, vf[0], vf[1]);
                mma_f16(O[2 * np + 1], af, vf[2], vf[3]);
            }
        }

        if (i + 2 < NB) issueKV(i + 2, (i + 2) % 3);
        buf = (buf == 2) ? 0 : buf + 1;
    }

    // ---- reduce l across the lane quad (cols split over 4 lanes) ----
    l0 += __shfl_xor_sync(0xffffffffu, l0, 1);
    l0 += __shfl_xor_sync(0xffffffffu, l0, 2);
    l1 += __shfl_xor_sync(0xffffffffu, l1, 1);
    l1 += __shfl_xor_sync(0xffffffffu, l1, 2);

    const float i0 = 1.f / l0;
    const float i1 = 1.f / l1;
    const int b_ = bh / NH, h_ = bh % NH;
    const int r0 = q0 + warp_m + gidx;
    __half* base = ctx + ((size_t)(b_ * TT) + r0) * DOUT + h_ * HD;
#pragma unroll
    for (int nf = 0; nf < 8; nf++) {
        *(uint32_t*)(base + nf * 8 + 2 * ctig) =
            packh2(O[nf][0] * i0, O[nf][1] * i0);
        *(uint32_t*)(base + (size_t)8 * DOUT + nf * 8 + 2 * ctig) =
            packh2(O[nf][2] * i1, O[nf][3] * i1);
    }
}

// ---------------------------------------------------------------------------
extern "C" void kernel_launch(void* const* d_in, const int* in_sizes, int n_in,
                              void* d_out, int out_size)
{
    const float* x  = (const float*)d_in[0];
    const float* Wq = (const float*)d_in[1];
    const float* Wk = (const float*)d_in[2];
    const float* Wv = (const float*)d_in[3];
    const float* Wo = (const float*)d_in[4];
    const float* bo = (const float*)d_in[5];
    float* out = (float*)d_out;

    __half *xh, *QKV, *Cp, *Wh, *WoH;
    cudaGetSymbolAddress((void**)&xh,  g_xh);
    cudaGetSymbolAddress((void**)&QKV, g_QKV);
    cudaGetSymbolAddress((void**)&Cp,  g_ctx);
    cudaGetSymbolAddress((void**)&Wh,  g_Wh);
    cudaGetSymbolAddress((void**)&WoH, g_WoH);

    constexpr int SMGEMM = (3 * 128 * 72 + 3 * 64 * 136) * 2;      // 107520 B
    constexpr int SMFA   = (128 * 72 + 6 * 64 * 72) * 2;           // 73728 B
    cudaFuncSetAttribute(gemm_h<0>, cudaFuncAttributeMaxDynamicSharedMemorySize, SMGEMM);
    cudaFuncSetAttribute(gemm_h<1>, cudaFuncAttributeMaxDynamicSharedMemorySize, SMGEMM);
    cudaFuncSetAttribute(flash_attn, cudaFuncAttributeMaxDynamicSharedMemorySize, SMFA);

    // preprocessing
    to_half<<<MROWS * DIN / 1024, 256>>>(x, xh);
    conv_w<<<dim3(DIN * DOUT / 1024, 1, 4), 256>>>(Wq, Wk, Wv, Wo, Wh, WoH);

    // fused QKV projection -> g_QKV [3][b,h,t,hd] fp16 (Q scaled 0.125*log2e)
    gemm_h<1><<<dim3(3 * DOUT / 128, MROWS / 128), 256, SMGEMM>>>(
        xh, Wh, nullptr, QKV, DIN, DIN, 3 * DOUT, 0);

    // fused flash attention -> ctx [b,t,d] fp16
    flash_attn<<<dim3(TT / 128, BB * NH), 256, SMFA>>>(
        QKV, QKV + QKVSZ, QKV + 2 * QKVSZ, Cp);

    // output projection + bias -> fp32 result
    gemm_h<0><<<dim3(DOUT / 128, MROWS / 128), 256, SMGEMM>>>(
        Cp, WoH, bo, out, DOUT, DOUT, DOUT, DOUT);
}